// round 3
// baseline (speedup 1.0000x reference)
#include <cuda_runtime.h>
#include <math.h>

#define Bb   8
#define LEAF 1024
#define Nn   2048
#define Dd   128
#define BN   (Bb * Nn)      // 16384
#define NCHUNK 16           // 2048 / 128

// Scratch (allocation-free rule: device globals)
__device__ float g_nf [BN * Dd];            // raw node features (tree means)
__device__ float g_h  [BN * Dd];            // gelu(LN(x))
__device__ float g_agg[BN * Dd];            // mean aggregation
__device__ float g_pre[BN * Dd];            // per-batch inclusive prefix of g_h
__device__ float g_ctot[Bb * NCHUNK * Dd];  // chunk totals for scan fixup
__device__ float g_enc[Nn * Dd];            // positional encoding table

// ---------------------------------------------------------------------------
// f32x2 packed helpers (SASS FFMA2 — PTX-only)
// ---------------------------------------------------------------------------
__device__ __forceinline__ unsigned long long pack2(float lo, float hi) {
    unsigned long long r;
    asm("mov.b64 %0, {%1, %2};" : "=l"(r) : "f"(lo), "f"(hi));
    return r;
}
__device__ __forceinline__ void unpack2(unsigned long long v, float& lo, float& hi) {
    asm("mov.b64 {%0, %1}, %2;" : "=f"(lo), "=f"(hi) : "l"(v));
}
__device__ __forceinline__ void ffma2(unsigned long long& d,
                                      unsigned long long a,
                                      unsigned long long b) {
    asm("fma.rn.f32x2 %0, %1, %2, %0;" : "+l"(d) : "l"(a), "l"(b));
}

// ---------------------------------------------------------------------------
// Tree build: pairwise mean up-sweep. Each thread owns one feature dim d.
// ---------------------------------------------------------------------------
__device__ __forceinline__ void reduce_store(const float v32[32], int bN, int base, int off, int d) {
    float v16[16];
#pragma unroll
    for (int j = 0; j < 16; j++) {
        v16[j] = 0.5f * (v32[2*j] + v32[2*j+1]);
        g_nf[(bN + (base >> 1) + (off >> 1) + j) * Dd + d] = v16[j];
    }
    float v8[8];
#pragma unroll
    for (int j = 0; j < 8; j++) {
        v8[j] = 0.5f * (v16[2*j] + v16[2*j+1]);
        g_nf[(bN + (base >> 2) + (off >> 2) + j) * Dd + d] = v8[j];
    }
    float v4[4];
#pragma unroll
    for (int j = 0; j < 4; j++) {
        v4[j] = 0.5f * (v8[2*j] + v8[2*j+1]);
        g_nf[(bN + (base >> 3) + (off >> 3) + j) * Dd + d] = v4[j];
    }
    float v2[2];
#pragma unroll
    for (int j = 0; j < 2; j++) {
        v2[j] = 0.5f * (v4[2*j] + v4[2*j+1]);
        g_nf[(bN + (base >> 4) + (off >> 4) + j) * Dd + d] = v2[j];
    }
    float v1 = 0.5f * (v2[0] + v2[1]);
    g_nf[(bN + (base >> 5) + (off >> 5)) * Dd + d] = v1;
}

__global__ void tree1_kernel(const float* __restrict__ elements) {
    int b = blockIdx.x >> 5;
    int s = blockIdx.x & 31;
    int d = threadIdx.x;
    int bN = b * Nn;
    float v32[32];
#pragma unroll
    for (int j = 0; j < 32; j++) {
        float v = elements[(b * LEAF + s * 32 + j) * Dd + d];
        v32[j] = v;
        g_nf[(bN + LEAF + s * 32 + j) * Dd + d] = v;
    }
    reduce_store(v32, bN, 1024, s * 32, d);
}

__global__ void tree2_kernel() {
    int b = blockIdx.x;
    int d = threadIdx.x;
    int bN = b * Nn;
    float v32[32];
#pragma unroll
    for (int j = 0; j < 32; j++)
        v32[j] = g_nf[(bN + 32 + j) * Dd + d];
    reduce_store(v32, bN, 32, 0, d);
    g_nf[bN * Dd + d] = -1.0f;  // global node 0
}

// ---------------------------------------------------------------------------
// Positional encoding table: depends only on node id (2048 rows)
// ---------------------------------------------------------------------------
__global__ void enc_kernel() {
    int node = blockIdx.x;
    int d = threadIdx.x;
    float pos;
    if (node == 0) {
        pos = (d < 64) ? -0.5f : -1.0f;   // hpos = -0.5, vpos = -1
    } else {
        int vp = 31 - __clz(node);
        pos = (d < 64) ? (float)(node - (1 << vp)) : (float)vp;
    }
    int dd = d & 63;
    int k = dd >> 1;
    float inv = expf(-0.28782313662425574f * (float)k);   // exp(-k*ln(1e4)/32)
    float ang = pos * inv;
    g_enc[node * Dd + d] = (dd & 1) ? cosf(ang) : sinf(ang);
}

// ---------------------------------------------------------------------------
// x = nf + enc; fused LN + exact GELU -> g_h (layer 0 input)
// ---------------------------------------------------------------------------
__global__ void encx_kernel(float* __restrict__ x,
                            const float* __restrict__ gamma,
                            const float* __restrict__ beta) {
    int gi = blockIdx.x;
    int node = gi & (Nn - 1);
    int d = threadIdx.x;
    float v = g_nf[gi * Dd + d] + g_enc[node * Dd + d];
    x[gi * Dd + d] = v;

    float s = v, s2 = v * v;
#pragma unroll
    for (int o = 16; o; o >>= 1) {
        s  += __shfl_xor_sync(0xffffffffu, s, o);
        s2 += __shfl_xor_sync(0xffffffffu, s2, o);
    }
    __shared__ float ss[4], ss2[4];
    int w = d >> 5, lane = d & 31;
    if (lane == 0) { ss[w] = s; ss2[w] = s2; }
    __syncthreads();
    s  = ss[0] + ss[1] + ss[2] + ss[3];
    s2 = ss2[0] + ss2[1] + ss2[2] + ss2[3];
    float mu  = s * (1.0f / 128.0f);
    float var = s2 * (1.0f / 128.0f) - mu * mu;
    float t = (v - mu) * rsqrtf(var + 1e-5f) * gamma[d] + beta[d];
    g_h[gi * Dd + d] = 0.5f * t * (1.0f + erff(t * 0.70710678118654752f));
}

// ---------------------------------------------------------------------------
// Per-batch inclusive prefix sum of g_h over node index (128-node chunks)
// ---------------------------------------------------------------------------
__global__ void scan1_kernel() {
    int b = blockIdx.x >> 4;
    int c = blockIdx.x & 15;
    int d = threadIdx.x;
    int base = b * Nn + c * 128;
    float acc = 0.f;
#pragma unroll 8
    for (int j = 0; j < 128; j++) {
        acc += g_h[(base + j) * Dd + d];
        g_pre[(base + j) * Dd + d] = acc;
    }
    g_ctot[(b * NCHUNK + c) * Dd + d] = acc;
}

__global__ void scan2_kernel() {
    int t = blockIdx.x;            // 0..119
    int b = t / 15;
    int c = 1 + t % 15;
    int d = threadIdx.x;
    float off = 0.f;
    for (int cp = 0; cp < c; cp++)
        off += g_ctot[(b * NCHUNK + cp) * Dd + d];
    int base = b * Nn + c * 128;
#pragma unroll 8
    for (int j = 0; j < 128; j++)
        g_pre[(base + j) * Dd + d] += off;
}

// ---------------------------------------------------------------------------
// Range-sum aggregation: each dst node's term list is a union of contiguous
// node-id ranges (bit-exact replication of the reference trace loops,
// including empty ranges and duplicated boundary terms).
//   range [a, e] sum = P[e] - P[a-1]   (global per-batch prefix; a >= 1)
// ---------------------------------------------------------------------------
__global__ void ragg_kernel() {
    int gi = blockIdx.x;
    int i  = gi & (Nn - 1);
    int d  = threadIdx.x;
    if (i == 0) {                       // global node: no in-edges, deg->1
        g_agg[gi * Dd + d] = 0.f;
        return;
    }
    const float* __restrict__ P = &g_pre[(gi - i) * Dd];   // batch base
    float acc = 0.f;
    int deg = 0;

    if (i < LEAF) {
        // internal node: descendant ranges [i<<k, ((i+1)<<k)-1]
        int a = i << 1;
        int e = (i << 1) | 1;
        while (e < Nn) {
            acc += P[e * Dd + d] - P[(a - 1) * Dd + d];
            deg += e - a + 1;
            a <<= 1;
            e = (e << 1) | 1;
        }
    } else {
        // leaf: trace_left then trace_right (ATTN=4, DEPTH=10)
        int ni = i, cd = 10;
        bool stop = false;
#pragma unroll 1
        for (int it = 0; it < 12 && !stop; it++) {
            int cs = (ni - 3) & ~1;
            stop = cs < (1 << cd);
            cs = max(cs, 1 << cd);
            if (ni >= cs) {
                acc += P[ni * Dd + d] - P[(cs - 1) * Dd + d];
                deg += ni - cs + 1;
            }
            ni = (cs - 1) >> 1;
            cd--;
        }
        ni = i; cd = 10; stop = false;
#pragma unroll 1
        for (int it = 0; it < 12 && !stop; it++) {
            int ce = ni + 3 + ((ni - 4) & 1);
            stop = ce >= (2 << cd);
            ce = min(ce, (2 << cd) - 1);
            if (ce >= ni) {
                acc += P[ce * Dd + d] - P[(ni - 1) * Dd + d];
                deg += ce - ni + 1;
            }
            ni = (ce + 1) >> 1;
            cd--;
        }
    }
    g_agg[gi * Dd + d] = acc / (float)(deg > 0 ? deg : 1);
}

// ---------------------------------------------------------------------------
// x += agg @ W1 + bias + h @ W2, f32x2 packed FMA.
// BM=64, BN=128 (full), BK=32, 128 threads, 8x8 micro-tile.
// FUSE: epilogue computes next layer's h = gelu(LN(x_new)) into g_h.
// ---------------------------------------------------------------------------
template<bool FUSE>
__global__ void __launch_bounds__(128) gemm_kernel(
    const float* __restrict__ W1, const float* __restrict__ W2,
    const float* __restrict__ bias,
    const float* __restrict__ gamma, const float* __restrict__ beta,
    float* __restrict__ X)
{
    __shared__ float As[32][64];
    __shared__ float Bs[32][128];
    const int bm = blockIdx.x * 64;
    const int tid = threadIdx.x;
    const int trow = tid >> 4;   // 0..7
    const int tcol = tid & 15;   // 0..15
    const int tm = trow * 8;
    const int tn = tcol * 8;

    unsigned long long acc[8][4];
#pragma unroll
    for (int i = 0; i < 8; i++)
#pragma unroll
        for (int j = 0; j < 4; j++) acc[i][j] = 0ull;

#pragma unroll
    for (int pass = 0; pass < 2; pass++) {
        const float* A = pass ? g_h : g_agg;
        const float* W = pass ? W2 : W1;
#pragma unroll
        for (int k0 = 0; k0 < Dd; k0 += 32) {
            {
                int m = tid >> 1, half = tid & 1;
                const float* ap = &A[(bm + m) * Dd + k0 + half * 16];
                float4 v0 = *(const float4*)(ap);
                float4 v1 = *(const float4*)(ap + 4);
                float4 v2 = *(const float4*)(ap + 8);
                float4 v3 = *(const float4*)(ap + 12);
                int kb = half * 16;
                As[kb+ 0][m] = v0.x; As[kb+ 1][m] = v0.y; As[kb+ 2][m] = v0.z; As[kb+ 3][m] = v0.w;
                As[kb+ 4][m] = v1.x; As[kb+ 5][m] = v1.y; As[kb+ 6][m] = v1.z; As[kb+ 7][m] = v1.w;
                As[kb+ 8][m] = v2.x; As[kb+ 9][m] = v2.y; As[kb+10][m] = v2.z; As[kb+11][m] = v2.w;
                As[kb+12][m] = v3.x; As[kb+13][m] = v3.y; As[kb+14][m] = v3.z; As[kb+15][m] = v3.w;
            }
            {
                int kk = tid >> 2, q = tid & 3;
                const float* wp = &W[(k0 + kk) * Dd + q * 32];
#pragma unroll
                for (int j = 0; j < 8; j++)
                    *(float4*)&Bs[kk][q * 32 + j * 4] = *(const float4*)(wp + j * 4);
            }
            __syncthreads();
#pragma unroll
            for (int kk = 0; kk < 32; kk++) {
                float4 a0 = *(const float4*)&As[kk][tm];
                float4 a1 = *(const float4*)&As[kk][tm + 4];
                float4 b0 = *(const float4*)&Bs[kk][tn];
                float4 b1 = *(const float4*)&Bs[kk][tn + 4];
                unsigned long long bp0 = pack2(b0.x, b0.y);
                unsigned long long bp1 = pack2(b0.z, b0.w);
                unsigned long long bp2 = pack2(b1.x, b1.y);
                unsigned long long bp3 = pack2(b1.z, b1.w);
                float af[8] = {a0.x, a0.y, a0.z, a0.w, a1.x, a1.y, a1.z, a1.w};
#pragma unroll
                for (int i = 0; i < 8; i++) {
                    unsigned long long ap = pack2(af[i], af[i]);
                    ffma2(acc[i][0], ap, bp0);
                    ffma2(acc[i][1], ap, bp1);
                    ffma2(acc[i][2], ap, bp2);
                    ffma2(acc[i][3], ap, bp3);
                }
            }
            __syncthreads();
        }
    }

    // Epilogue
    float bb[8], gg[8], be[8];
#pragma unroll
    for (int j = 0; j < 8; j++) bb[j] = bias[tn + j];
    if (FUSE) {
#pragma unroll
        for (int j = 0; j < 8; j++) { gg[j] = gamma[tn + j]; be[j] = beta[tn + j]; }
    }
#pragma unroll
    for (int i = 0; i < 8; i++) {
        int row = bm + tm + i;
        float4 x0 = *(const float4*)&X[row * Dd + tn];
        float4 x1 = *(const float4*)&X[row * Dd + tn + 4];
        float xv[8] = {x0.x, x0.y, x0.z, x0.w, x1.x, x1.y, x1.z, x1.w};
#pragma unroll
        for (int j = 0; j < 4; j++) {
            float lo, hi;
            unpack2(acc[i][j], lo, hi);
            xv[2*j]   += lo + bb[2*j];
            xv[2*j+1] += hi + bb[2*j+1];
        }
        x0 = make_float4(xv[0], xv[1], xv[2], xv[3]);
        x1 = make_float4(xv[4], xv[5], xv[6], xv[7]);
        *(float4*)&X[row * Dd + tn]     = x0;
        *(float4*)&X[row * Dd + tn + 4] = x1;
        if (FUSE) {
            float s = 0.f, s2 = 0.f;
#pragma unroll
            for (int j = 0; j < 8; j++) { s += xv[j]; s2 += xv[j] * xv[j]; }
#pragma unroll
            for (int o = 1; o <= 8; o <<= 1) {
                s  += __shfl_xor_sync(0xffffffffu, s, o);
                s2 += __shfl_xor_sync(0xffffffffu, s2, o);
            }
            float mu  = s * (1.0f / 128.0f);
            float var = s2 * (1.0f / 128.0f) - mu * mu;
            float rs  = rsqrtf(var + 1e-5f);
            float hv[8];
#pragma unroll
            for (int j = 0; j < 8; j++) {
                float t = (xv[j] - mu) * rs * gg[j] + be[j];
                hv[j] = 0.5f * t * (1.0f + erff(t * 0.70710678118654752f));
            }
            *(float4*)&g_h[row * Dd + tn]     = make_float4(hv[0], hv[1], hv[2], hv[3]);
            *(float4*)&g_h[row * Dd + tn + 4] = make_float4(hv[4], hv[5], hv[6], hv[7]);
        }
    }
}

// ---------------------------------------------------------------------------
extern "C" void kernel_launch(void* const* d_in, const int* in_sizes, int n_in,
                              void* d_out, int out_size) {
    const float* elements = (const float*)d_in[0];
    const float* ln_gamma = (const float*)d_in[1];
    const float* ln_beta  = (const float*)d_in[2];
    const float* w_nei    = (const float*)d_in[3];
    const float* b_nei    = (const float*)d_in[4];
    const float* w_root   = (const float*)d_in[5];
    float* x = (float*)d_out;

    tree1_kernel<<<Bb * 32, Dd>>>(elements);
    tree2_kernel<<<Bb, Dd>>>();
    enc_kernel<<<Nn, Dd>>>();
    encx_kernel<<<BN, Dd>>>(x, ln_gamma, ln_beta);

    // layer 0 (gemm fuses LN+GELU for layer 1 into its epilogue)
    scan1_kernel<<<Bb * NCHUNK, Dd>>>();
    scan2_kernel<<<Bb * (NCHUNK - 1), Dd>>>();
    ragg_kernel<<<BN, Dd>>>();
    gemm_kernel<true><<<BN / 64, 128>>>(w_nei, w_root, b_nei,
                                        ln_gamma + Dd, ln_beta + Dd, x);

    // layer 1 (final — no fused LN)
    scan1_kernel<<<Bb * NCHUNK, Dd>>>();
    scan2_kernel<<<Bb * (NCHUNK - 1), Dd>>>();
    ragg_kernel<<<BN, Dd>>>();
    gemm_kernel<false><<<BN / 64, 128>>>(w_nei + Dd * Dd, w_root + Dd * Dd,
                                         b_nei + Dd, nullptr, nullptr, x);
}

// round 5
// speedup vs baseline: 1.4579x; 1.4579x over previous
#include <cuda_runtime.h>
#include <math.h>

#define Bb   8
#define LEAF 1024
#define Nn   2048
#define Dd   128
#define BN   (Bb * Nn)      // 16384
#define HEAVY_PER_B 15      // locals 1..15 have deg > 128
#define HCHUNKS 16          // 16 chunks x 128 edges covers deg <= 2046
#define HEAVY_W (Bb * HEAVY_PER_B * HCHUNKS)   // 1920

// Scratch (allocation-free rule: device globals)
__device__ float g_nf  [BN * Dd];          // raw node features (tree means)
__device__ float g_h   [BN * Dd];          // gelu(LN(x))
__device__ float g_agg [BN * Dd];          // mean aggregation
__device__ float g_part[HEAVY_W * Dd];     // heavy-node partial sums

// ---------------------------------------------------------------------------
// f32x2 packed helpers (SASS FFMA2 — PTX-only)
// ---------------------------------------------------------------------------
__device__ __forceinline__ unsigned long long pack2(float lo, float hi) {
    unsigned long long r;
    asm("mov.b64 %0, {%1, %2};" : "=l"(r) : "f"(lo), "f"(hi));
    return r;
}
__device__ __forceinline__ void unpack2(unsigned long long v, float& lo, float& hi) {
    asm("mov.b64 {%0, %1}, %2;" : "=f"(lo), "=f"(hi) : "l"(v));
}
__device__ __forceinline__ void ffma2(unsigned long long& d,
                                      unsigned long long a,
                                      unsigned long long b) {
    asm("fma.rn.f32x2 %0, %1, %2, %0;" : "+l"(d) : "l"(a), "l"(b));
}

// ---------------------------------------------------------------------------
// Tree build: pairwise mean up-sweep. Each thread owns one feature dim d.
// ---------------------------------------------------------------------------
__device__ __forceinline__ void reduce_store(const float v32[32], int bN, int base, int off, int d) {
    float v16[16];
#pragma unroll
    for (int j = 0; j < 16; j++) {
        v16[j] = 0.5f * (v32[2*j] + v32[2*j+1]);
        g_nf[(bN + (base >> 1) + (off >> 1) + j) * Dd + d] = v16[j];
    }
    float v8[8];
#pragma unroll
    for (int j = 0; j < 8; j++) {
        v8[j] = 0.5f * (v16[2*j] + v16[2*j+1]);
        g_nf[(bN + (base >> 2) + (off >> 2) + j) * Dd + d] = v8[j];
    }
    float v4[4];
#pragma unroll
    for (int j = 0; j < 4; j++) {
        v4[j] = 0.5f * (v8[2*j] + v8[2*j+1]);
        g_nf[(bN + (base >> 3) + (off >> 3) + j) * Dd + d] = v4[j];
    }
    float v2[2];
#pragma unroll
    for (int j = 0; j < 2; j++) {
        v2[j] = 0.5f * (v4[2*j] + v4[2*j+1]);
        g_nf[(bN + (base >> 4) + (off >> 4) + j) * Dd + d] = v2[j];
    }
    float v1 = 0.5f * (v2[0] + v2[1]);
    g_nf[(bN + (base >> 5) + (off >> 5)) * Dd + d] = v1;
}

__global__ void tree1_kernel(const float* __restrict__ elements) {
    int b = blockIdx.x >> 5;
    int s = blockIdx.x & 31;
    int d = threadIdx.x;
    int bN = b * Nn;
    float v32[32];
#pragma unroll
    for (int j = 0; j < 32; j++) {
        float v = elements[(b * LEAF + s * 32 + j) * Dd + d];
        v32[j] = v;
        g_nf[(bN + LEAF + s * 32 + j) * Dd + d] = v;
    }
    reduce_store(v32, bN, 1024, s * 32, d);
}

__global__ void tree2_kernel() {
    int b = blockIdx.x;
    int d = threadIdx.x;
    int bN = b * Nn;
    float v32[32];
#pragma unroll
    for (int j = 0; j < 32; j++)
        v32[j] = g_nf[(bN + 32 + j) * Dd + d];
    reduce_store(v32, bN, 32, 0, d);
    g_nf[bN * Dd + d] = -1.0f;  // global node 0
}

// ---------------------------------------------------------------------------
// x = nf + positional encoding; fused LN + exact GELU -> g_h (layer 0 input)
// ---------------------------------------------------------------------------
__global__ void encx_kernel(float* __restrict__ x,
                            const float* __restrict__ gamma,
                            const float* __restrict__ beta) {
    int gi = blockIdx.x;
    int node = gi & (Nn - 1);
    int d = threadIdx.x;
    float pos;
    if (node == 0) {
        pos = (d < 64) ? -0.5f : -1.0f;
    } else {
        int vp = 31 - __clz(node);
        pos = (d < 64) ? (float)(node - (1 << vp)) : (float)vp;
    }
    int dd = d & 63;
    int k = dd >> 1;
    float inv = expf(-0.28782313662425574f * (float)k);   // exp(-k*ln(1e4)/32)
    float ang = pos * inv;
    float e = (dd & 1) ? cosf(ang) : sinf(ang);
    float v = g_nf[gi * Dd + d] + e;
    x[gi * Dd + d] = v;

    float s = v, s2 = v * v;
#pragma unroll
    for (int o = 16; o; o >>= 1) {
        s  += __shfl_xor_sync(0xffffffffu, s, o);
        s2 += __shfl_xor_sync(0xffffffffu, s2, o);
    }
    __shared__ float ss[4], ss2[4];
    int w = d >> 5, lane = d & 31;
    if (lane == 0) { ss[w] = s; ss2[w] = s2; }
    __syncthreads();
    s  = ss[0] + ss[1] + ss[2] + ss[3];
    s2 = ss2[0] + ss2[1] + ss2[2] + ss2[3];
    float mu  = s * (1.0f / 128.0f);
    float var = s2 * (1.0f / 128.0f) - mu * mu;
    float t = (v - mu) * rsqrtf(var + 1e-5f) * gamma[d] + beta[d];
    g_h[gi * Dd + d] = 0.5f * t * (1.0f + erff(t * 0.70710678118654752f));
}

// ---------------------------------------------------------------------------
// Aggregation: structural edge enumeration (no edge_index needed).
// Each block builds its dst node's term list in smem (bit-exact replication
// of the reference trace loops, incl. duplicate boundary terms), then does a
// 4-group float4 gather over g_h rows.
//   blocks [0, BN):       one node each (heavy locals 1..15 skipped)
//   blocks [BN, BN+1920): heavy-node 128-edge chunks -> g_part
// NOTE: sbuf/slist are 16B-aligned; sbuf is accessed as float4 (r4 crash fix).
// ---------------------------------------------------------------------------
__global__ void agg_kernel() {
    __shared__ __align__(16) float sbuf[4 * Dd];
    __shared__ __align__(16) int   slist[160];
    __shared__ int   sL;
    int bid = blockIdx.x;
    int tid = threadIdx.x;
    int g = tid >> 5, l = tid & 31;
    int bbase, L;
    float scale;
    float* out;

    if (bid < BN) {
        int local = bid & (Nn - 1);
        if (local >= 1 && local <= HEAVY_PER_B) return;   // heavy path handles
        bbase = bid - local;
        if (tid == 0) {
            int cnt = 0;
            if (local == 0) {
                // global node: no in-edges
            } else if (local < LEAF) {
                // internal node: descendant ranges level by level
                int dv = 31 - __clz(local);
                for (int k = 1; k <= 10 - dv; k++) {
                    int s0 = local << k;
                    for (int j = 0; j < (1 << k); j++) slist[cnt++] = s0 + j;
                }
            } else {
                // leaf: trace_left then trace_right (ATTN=4, DEPTH=10)
                int ni = local, cd = 10;
                bool stop = false;
                while (!stop) {
                    int cs = (ni - 3) & ~1;
                    stop = cs < (1 << cd);
                    cs = max(cs, 1 << cd);
                    for (int t = cs; t <= ni; t++) slist[cnt++] = t;
                    ni = (cs - 1) >> 1;
                    cd--;
                }
                ni = local; cd = 10; stop = false;
                while (!stop) {
                    int ce = ni + 3 + ((ni - 4) & 1);
                    stop = ce >= (2 << cd);
                    ce = min(ce, (2 << cd) - 1);
                    for (int t = ni; t <= ce; t++) slist[cnt++] = t;
                    ni = (ce + 1) >> 1;
                    cd--;
                }
            }
            sL = cnt;
        }
        out = &g_agg[bid * Dd];
        __syncthreads();
        L = sL;
        scale = 1.0f / (float)(L > 0 ? L : 1);
    } else {
        int w = bid - BN;
        int b = w / (HEAVY_PER_B * HCHUNKS);
        int r = w % (HEAVY_PER_B * HCHUNKS);
        int local = 1 + (r >> 4);
        int c = r & 15;
        bbase = b * Nn;
        int dv = 31 - __clz(local);
        int deg = (1 << (11 - dv)) - 2;
        int t0 = c * 128, t1 = min(deg, t0 + 128);
        if (tid == 0) {
            int cnt = 0;
            // flat term index t -> level k = ilog2(t+2), node = (local<<k) + (t+2-2^k)
            for (int t = t0; t < t1; t++) {
                int k = 31 - __clz(t + 2);
                slist[cnt++] = (local << k) + (t + 2 - (1 << k));
            }
            sL = cnt;
        }
        out = &g_part[w * Dd];
        __syncthreads();
        L = sL;
        scale = 1.0f;
    }

    float4 acc = make_float4(0.f, 0.f, 0.f, 0.f);
    int t = g;
    for (; t + 4 < L; t += 8) {
        int i0 = slist[t];
        int i1 = slist[t + 4];
        float4 v0 = *(const float4*)&g_h[(bbase + i0) * Dd + l * 4];
        float4 v1 = *(const float4*)&g_h[(bbase + i1) * Dd + l * 4];
        acc.x += v0.x + v1.x;
        acc.y += v0.y + v1.y;
        acc.z += v0.z + v1.z;
        acc.w += v0.w + v1.w;
    }
    if (t < L) {
        int i0 = slist[t];
        float4 v0 = *(const float4*)&g_h[(bbase + i0) * Dd + l * 4];
        acc.x += v0.x; acc.y += v0.y; acc.z += v0.z; acc.w += v0.w;
    }
    *(float4*)&sbuf[g * Dd + l * 4] = acc;
    __syncthreads();
    float v = sbuf[tid] + sbuf[Dd + tid] + sbuf[2 * Dd + tid] + sbuf[3 * Dd + tid];
    out[tid] = v * scale;
}

// Deterministic fixup: sum the 16 partials of each heavy node in fixed order.
__global__ void aggfix_kernel() {
    int b = blockIdx.x / HEAVY_PER_B;
    int r = blockIdx.x % HEAVY_PER_B;
    int local = r + 1;
    int t = threadIdx.x;
    float sum = 0.f;
#pragma unroll
    for (int c = 0; c < HCHUNKS; c++)
        sum += g_part[((b * HEAVY_PER_B + r) * HCHUNKS + c) * Dd + t];
    int dv = 31 - __clz(local);
    int deg = (1 << (11 - dv)) - 2;
    g_agg[(b * Nn + local) * Dd + t] = sum / (float)deg;
}

// ---------------------------------------------------------------------------
// x += agg @ W1 + bias + h @ W2, f32x2 packed FMA with zero in-loop packing:
// A tile stored as duplicated (a,a) 8B pairs; B pairs loaded via ulonglong2.
// BM=64, BN=128 (full), BK=32, 128 threads, 8x8 micro-tile.
// FUSE: epilogue computes next layer's h = gelu(LN(x_new)) into g_h.
// ---------------------------------------------------------------------------
template<bool FUSE>
__global__ void __launch_bounds__(128) gemm_kernel(
    const float* __restrict__ W1, const float* __restrict__ W2,
    const float* __restrict__ bias,
    const float* __restrict__ gamma, const float* __restrict__ beta,
    float* __restrict__ X)
{
    __shared__ __align__(16) unsigned long long As2[32][64];   // 16 KB, (a,a) pairs
    __shared__ __align__(16) float Bs[32][128];                // 16 KB
    const int bm = blockIdx.x * 64;
    const int tid = threadIdx.x;
    const int trow = tid >> 4;   // 0..7
    const int tcol = tid & 15;   // 0..15
    const int tm = trow * 8;
    const int tn = tcol * 8;

    unsigned long long acc[8][4];
#pragma unroll
    for (int i = 0; i < 8; i++)
#pragma unroll
        for (int j = 0; j < 4; j++) acc[i][j] = 0ull;

#pragma unroll
    for (int pass = 0; pass < 2; pass++) {
        const float* A = pass ? g_h : g_agg;
        const float* W = pass ? W2 : W1;
#pragma unroll
        for (int k0 = 0; k0 < Dd; k0 += 32) {
            // A tile [64 x 32] -> As2[kk][m] duplicated pairs
            {
                int m = tid >> 1, half = tid & 1;
                const float* ap = &A[(bm + m) * Dd + k0 + half * 16];
                int kb = half * 16;
#pragma unroll
                for (int j = 0; j < 4; j++) {
                    float4 v = *(const float4*)(ap + j * 4);
                    As2[kb + j*4 + 0][m] = pack2(v.x, v.x);
                    As2[kb + j*4 + 1][m] = pack2(v.y, v.y);
                    As2[kb + j*4 + 2][m] = pack2(v.z, v.z);
                    As2[kb + j*4 + 3][m] = pack2(v.w, v.w);
                }
            }
            // B tile [32 x 128]
            {
                int kk = tid >> 2, q = tid & 3;
                const float* wp = &W[(k0 + kk) * Dd + q * 32];
#pragma unroll
                for (int j = 0; j < 8; j++)
                    *(float4*)&Bs[kk][q * 32 + j * 4] = *(const float4*)(wp + j * 4);
            }
            __syncthreads();
#pragma unroll
            for (int kk = 0; kk < 32; kk++) {
                ulonglong2 a01 = *(const ulonglong2*)&As2[kk][tm];
                ulonglong2 a23 = *(const ulonglong2*)&As2[kk][tm + 2];
                ulonglong2 a45 = *(const ulonglong2*)&As2[kk][tm + 4];
                ulonglong2 a67 = *(const ulonglong2*)&As2[kk][tm + 6];
                ulonglong2 b01 = *(const ulonglong2*)&Bs[kk][tn];
                ulonglong2 b23 = *(const ulonglong2*)&Bs[kk][tn + 4];
                unsigned long long ap[8] = {a01.x, a01.y, a23.x, a23.y,
                                            a45.x, a45.y, a67.x, a67.y};
                unsigned long long bp[4] = {b01.x, b01.y, b23.x, b23.y};
#pragma unroll
                for (int i = 0; i < 8; i++) {
                    ffma2(acc[i][0], ap[i], bp[0]);
                    ffma2(acc[i][1], ap[i], bp[1]);
                    ffma2(acc[i][2], ap[i], bp[2]);
                    ffma2(acc[i][3], ap[i], bp[3]);
                }
            }
            __syncthreads();
        }
    }

    // Epilogue
    float bb[8], gg[8], be[8];
#pragma unroll
    for (int j = 0; j < 8; j++) bb[j] = bias[tn + j];
    if (FUSE) {
#pragma unroll
        for (int j = 0; j < 8; j++) { gg[j] = gamma[tn + j]; be[j] = beta[tn + j]; }
    }
#pragma unroll
    for (int i = 0; i < 8; i++) {
        int row = bm + tm + i;
        float4 x0 = *(const float4*)&X[row * Dd + tn];
        float4 x1 = *(const float4*)&X[row * Dd + tn + 4];
        float xv[8] = {x0.x, x0.y, x0.z, x0.w, x1.x, x1.y, x1.z, x1.w};
#pragma unroll
        for (int j = 0; j < 4; j++) {
            float lo, hi;
            unpack2(acc[i][j], lo, hi);
            xv[2*j]   += lo + bb[2*j];
            xv[2*j+1] += hi + bb[2*j+1];
        }
        x0 = make_float4(xv[0], xv[1], xv[2], xv[3]);
        x1 = make_float4(xv[4], xv[5], xv[6], xv[7]);
        *(float4*)&X[row * Dd + tn]     = x0;
        *(float4*)&X[row * Dd + tn + 4] = x1;
        if (FUSE) {
            float s = 0.f, s2 = 0.f;
#pragma unroll
            for (int j = 0; j < 8; j++) { s += xv[j]; s2 += xv[j] * xv[j]; }
#pragma unroll
            for (int o = 1; o <= 8; o <<= 1) {
                s  += __shfl_xor_sync(0xffffffffu, s, o);
                s2 += __shfl_xor_sync(0xffffffffu, s2, o);
            }
            float mu  = s * (1.0f / 128.0f);
            float var = s2 * (1.0f / 128.0f) - mu * mu;
            float rs  = rsqrtf(var + 1e-5f);
            float hv[8];
#pragma unroll
            for (int j = 0; j < 8; j++) {
                float t = (xv[j] - mu) * rs * gg[j] + be[j];
                hv[j] = 0.5f * t * (1.0f + erff(t * 0.70710678118654752f));
            }
            *(float4*)&g_h[row * Dd + tn]     = make_float4(hv[0], hv[1], hv[2], hv[3]);
            *(float4*)&g_h[row * Dd + tn + 4] = make_float4(hv[4], hv[5], hv[6], hv[7]);
        }
    }
}

// ---------------------------------------------------------------------------
extern "C" void kernel_launch(void* const* d_in, const int* in_sizes, int n_in,
                              void* d_out, int out_size) {
    const float* elements = (const float*)d_in[0];
    const float* ln_gamma = (const float*)d_in[1];
    const float* ln_beta  = (const float*)d_in[2];
    const float* w_nei    = (const float*)d_in[3];
    const float* b_nei    = (const float*)d_in[4];
    const float* w_root   = (const float*)d_in[5];
    float* x = (float*)d_out;

    tree1_kernel<<<Bb * 32, Dd>>>(elements);                       // 1
    tree2_kernel<<<Bb, Dd>>>();                                    // 2
    encx_kernel<<<BN, Dd>>>(x, ln_gamma, ln_beta);                 // 3

    // layer 0 (gemm fuses LN+GELU for layer 1 into its epilogue)
    agg_kernel<<<BN + HEAVY_W, Dd>>>();                            // 4 (profiled)
    aggfix_kernel<<<Bb * HEAVY_PER_B, Dd>>>();                     // 5
    gemm_kernel<true><<<BN / 64, 128>>>(w_nei, w_root, b_nei,
                                        ln_gamma + Dd, ln_beta + Dd, x);

    // layer 1 (final — no fused LN)
    agg_kernel<<<BN + HEAVY_W, Dd>>>();
    aggfix_kernel<<<Bb * HEAVY_PER_B, Dd>>>();
    gemm_kernel<false><<<BN / 64, 128>>>(w_nei + Dd * Dd, w_root + Dd * Dd,
                                         b_nei + Dd, nullptr, nullptr, x);
}

// round 6
// speedup vs baseline: 1.5612x; 1.0709x over previous
#include <cuda_runtime.h>
#include <math.h>

#define Bb   8
#define LEAF 1024
#define Nn   2048
#define Dd   128
#define BN   (Bb * Nn)      // 16384
#define SFLAG 0x10000       // slist entry flag: row comes from g_Stop

// Scratch (allocation-free rule: device globals)
__device__ float g_nf  [BN * Dd];          // raw node features (tree means)
__device__ float g_h   [BN * Dd];          // gelu(LN(x))
__device__ float g_agg [BN * Dd];          // mean aggregation
__device__ float g_Stop[Bb * 32 * Dd];     // raw subtree sums S(32..63) per batch

// ---------------------------------------------------------------------------
// f32x2 packed helpers (SASS FFMA2 — PTX-only)
// ---------------------------------------------------------------------------
__device__ __forceinline__ unsigned long long pack2(float lo, float hi) {
    unsigned long long r;
    asm("mov.b64 %0, {%1, %2};" : "=l"(r) : "f"(lo), "f"(hi));
    return r;
}
__device__ __forceinline__ void unpack2(unsigned long long v, float& lo, float& hi) {
    asm("mov.b64 {%0, %1}, %2;" : "=f"(lo), "=f"(hi) : "l"(v));
}
__device__ __forceinline__ void ffma2(unsigned long long& d,
                                      unsigned long long a,
                                      unsigned long long b) {
    asm("fma.rn.f32x2 %0, %1, %2, %0;" : "+l"(d) : "l"(a), "l"(b));
}

// ---------------------------------------------------------------------------
// Tree build: pairwise mean up-sweep. Each thread owns one feature dim d.
// ---------------------------------------------------------------------------
__device__ __forceinline__ void reduce_store(const float v32[32], int bN, int base, int off, int d) {
    float v16[16];
#pragma unroll
    for (int j = 0; j < 16; j++) {
        v16[j] = 0.5f * (v32[2*j] + v32[2*j+1]);
        g_nf[(bN + (base >> 1) + (off >> 1) + j) * Dd + d] = v16[j];
    }
    float v8[8];
#pragma unroll
    for (int j = 0; j < 8; j++) {
        v8[j] = 0.5f * (v16[2*j] + v16[2*j+1]);
        g_nf[(bN + (base >> 2) + (off >> 2) + j) * Dd + d] = v8[j];
    }
    float v4[4];
#pragma unroll
    for (int j = 0; j < 4; j++) {
        v4[j] = 0.5f * (v8[2*j] + v8[2*j+1]);
        g_nf[(bN + (base >> 3) + (off >> 3) + j) * Dd + d] = v4[j];
    }
    float v2[2];
#pragma unroll
    for (int j = 0; j < 2; j++) {
        v2[j] = 0.5f * (v4[2*j] + v4[2*j+1]);
        g_nf[(bN + (base >> 4) + (off >> 4) + j) * Dd + d] = v2[j];
    }
    float v1 = 0.5f * (v2[0] + v2[1]);
    g_nf[(bN + (base >> 5) + (off >> 5)) * Dd + d] = v1;
}

__global__ void tree1_kernel(const float* __restrict__ elements) {
    int b = blockIdx.x >> 5;
    int s = blockIdx.x & 31;
    int d = threadIdx.x;
    int bN = b * Nn;
    float v32[32];
#pragma unroll
    for (int j = 0; j < 32; j++) {
        float v = elements[(b * LEAF + s * 32 + j) * Dd + d];
        v32[j] = v;
        g_nf[(bN + LEAF + s * 32 + j) * Dd + d] = v;
    }
    reduce_store(v32, bN, 1024, s * 32, d);
}

__global__ void tree2_kernel() {
    int b = blockIdx.x;
    int d = threadIdx.x;
    int bN = b * Nn;
    float v32[32];
#pragma unroll
    for (int j = 0; j < 32; j++)
        v32[j] = g_nf[(bN + 32 + j) * Dd + d];
    reduce_store(v32, bN, 32, 0, d);
    g_nf[bN * Dd + d] = -1.0f;  // global node 0
}

// ---------------------------------------------------------------------------
// x = nf + positional encoding; fused LN + exact GELU -> g_h (layer 0 input)
// ---------------------------------------------------------------------------
__global__ void encx_kernel(float* __restrict__ x,
                            const float* __restrict__ gamma,
                            const float* __restrict__ beta) {
    int gi = blockIdx.x;
    int node = gi & (Nn - 1);
    int d = threadIdx.x;
    float pos;
    if (node == 0) {
        pos = (d < 64) ? -0.5f : -1.0f;
    } else {
        int vp = 31 - __clz(node);
        pos = (d < 64) ? (float)(node - (1 << vp)) : (float)vp;
    }
    int dd = d & 63;
    int k = dd >> 1;
    float inv = expf(-0.28782313662425574f * (float)k);   // exp(-k*ln(1e4)/32)
    float ang = pos * inv;
    float e = (dd & 1) ? cosf(ang) : sinf(ang);
    float v = g_nf[gi * Dd + d] + e;
    x[gi * Dd + d] = v;

    float s = v, s2 = v * v;
#pragma unroll
    for (int o = 16; o; o >>= 1) {
        s  += __shfl_xor_sync(0xffffffffu, s, o);
        s2 += __shfl_xor_sync(0xffffffffu, s2, o);
    }
    __shared__ float ss[4], ss2[4];
    int w = d >> 5, lane = d & 31;
    if (lane == 0) { ss[w] = s; ss2[w] = s2; }
    __syncthreads();
    s  = ss[0] + ss[1] + ss[2] + ss[3];
    s2 = ss2[0] + ss2[1] + ss2[2] + ss2[3];
    float mu  = s * (1.0f / 128.0f);
    float var = s2 * (1.0f / 128.0f) - mu * mu;
    float t = (v - mu) * rsqrtf(var + 1e-5f) * gamma[d] + beta[d];
    g_h[gi * Dd + d] = 0.5f * t * (1.0f + erff(t * 0.70710678118654752f));
}

// ---------------------------------------------------------------------------
// S up-sweep: S(i) = sum of h over ALL strict descendants of i.
// Blocks 0..255: (batch b, 32-leaf subtree s) -> writes agg = S/deg for the
// 31 internal nodes at levels 5..9 of the subtree, plus raw S(32+s) -> g_Stop.
// Blocks 256..263: zero agg row of global node 0 per batch.
// ---------------------------------------------------------------------------
__global__ void s1_kernel() {
    int bid = blockIdx.x;
    int d = threadIdx.x;
    if (bid >= 256) {
        int b = bid - 256;
        g_agg[(b * Nn) * Dd + d] = 0.f;
        return;
    }
    int b = bid >> 5;
    int s = bid & 31;
    int bN = b * Nn;

    float hv[32];
#pragma unroll
    for (int j = 0; j < 32; j++)
        hv[j] = g_h[(bN + LEAF + s * 32 + j) * Dd + d];

    // level 9 (nodes 512+16s+j): S = leaf pair sums, deg = 2
    float S9[16];
#pragma unroll
    for (int j = 0; j < 16; j++) {
        S9[j] = hv[2*j] + hv[2*j+1];
        g_agg[(bN + 512 + 16*s + j) * Dd + d] = S9[j] * 0.5f;
    }
    // level 8, deg = 6
    float S8[8];
#pragma unroll
    for (int j = 0; j < 8; j++) {
        float h0 = g_h[(bN + 512 + 16*s + 2*j) * Dd + d];
        float h1 = g_h[(bN + 512 + 16*s + 2*j + 1) * Dd + d];
        S8[j] = (h0 + S9[2*j]) + (h1 + S9[2*j+1]);
        g_agg[(bN + 256 + 8*s + j) * Dd + d] = S8[j] * (1.0f / 6.0f);
    }
    // level 7, deg = 14
    float S7[4];
#pragma unroll
    for (int j = 0; j < 4; j++) {
        float h0 = g_h[(bN + 256 + 8*s + 2*j) * Dd + d];
        float h1 = g_h[(bN + 256 + 8*s + 2*j + 1) * Dd + d];
        S7[j] = (h0 + S8[2*j]) + (h1 + S8[2*j+1]);
        g_agg[(bN + 128 + 4*s + j) * Dd + d] = S7[j] * (1.0f / 14.0f);
    }
    // level 6, deg = 30
    float S6[2];
#pragma unroll
    for (int j = 0; j < 2; j++) {
        float h0 = g_h[(bN + 128 + 4*s + 2*j) * Dd + d];
        float h1 = g_h[(bN + 128 + 4*s + 2*j + 1) * Dd + d];
        S6[j] = (h0 + S7[2*j]) + (h1 + S7[2*j+1]);
        g_agg[(bN + 64 + 2*s + j) * Dd + d] = S6[j] * (1.0f / 30.0f);
    }
    // level 5 (node 32+s), deg = 62
    {
        float h0 = g_h[(bN + 64 + 2*s) * Dd + d];
        float h1 = g_h[(bN + 64 + 2*s + 1) * Dd + d];
        float S5 = (h0 + S6[0]) + (h1 + S6[1]);
        g_agg[(bN + 32 + s) * Dd + d] = S5 * (1.0f / 62.0f);
        g_Stop[(b * 32 + s) * Dd + d] = S5;
    }
}

// ---------------------------------------------------------------------------
// Gather aggregation for leaves (window traces) and mid nodes 1..31.
//   blocks [0, 8192):     leaf nodes (1024 + idx) of batch idx>>10
//   blocks [8192, 8440):  mid nodes 1..31 (h-descendants + level-5 S rows)
// Segment bounds built by tid0 (<=16 serial iters), list expanded in parallel.
// ---------------------------------------------------------------------------
__global__ void aggall_kernel() {
    __shared__ __align__(16) float sbuf[4 * Dd];
    __shared__ __align__(16) int   slist[160];
    __shared__ int   segS[26], segP[26];
    __shared__ int   sNseg, sL;
    __shared__ float sInv;

    int bid = blockIdx.x;
    int tid = threadIdx.x;
    int g = tid >> 5, l = tid & 31;
    int b, local;
    if (bid < 8192) { b = bid >> 10; local = LEAF + (bid & 1023); }
    else            { int w = bid - 8192; b = w / 31; local = 1 + w % 31; }
    int bN = b * Nn;

    if (tid == 0) {
        if (local >= LEAF) {
            // leaf: compute segment bounds only (exact reference trace loops)
            int nseg = 0, tot = 0;
            int ni = local, cd = 10;
            bool stop = false;
            while (!stop) {
                int cs = (ni - 3) & ~1;
                stop = cs < (1 << cd);
                cs = max(cs, 1 << cd);
                segS[nseg] = cs; segP[nseg] = tot;
                tot += ni - cs + 1; nseg++;
                ni = (cs - 1) >> 1;
                cd--;
            }
            ni = local; cd = 10; stop = false;
            while (!stop) {
                int ce = ni + 3 + ((ni - 4) & 1);
                stop = ce >= (2 << cd);
                ce = min(ce, (2 << cd) - 1);
                segS[nseg] = ni; segP[nseg] = tot;
                tot += ce - ni + 1; nseg++;
                ni = (ce + 1) >> 1;
                cd--;
            }
            segP[nseg] = tot;
            sNseg = nseg; sL = tot;
            sInv = 1.0f / (float)tot;
        } else {
            // mid node 1..31: descendants' h (levels lvl+1..5) + level-5 S rows
            int lvl = 31 - __clz(local);
            int cnt = 0;
            for (int k = 1; k <= 5 - lvl; k++) {
                int s0 = local << k;
                for (int j = 0; j < (1 << k); j++) slist[cnt++] = s0 + j;
            }
            int s5 = local << (5 - lvl);
            for (int j = 0; j < (1 << (5 - lvl)); j++)
                slist[cnt++] = SFLAG | (s5 + j);
            sNseg = 0; sL = cnt;
            int deg = (1 << (11 - lvl)) - 2;
            sInv = 1.0f / (float)deg;
        }
    }
    __syncthreads();

    int L = sL;
    // parallel list expansion for leaves
    if (sNseg > 0) {
        int nseg = sNseg;
        for (int t = tid; t < L; t += 128) {
            int s = 0;
            while (s + 1 < nseg && segP[s + 1] <= t) s++;
            slist[t] = segS[s] + (t - segP[s]);
        }
        __syncthreads();
    }

    const float* __restrict__ hbase = &g_h[bN * Dd];
    const float* __restrict__ sbase = &g_Stop[b * 32 * Dd];

    float4 acc = make_float4(0.f, 0.f, 0.f, 0.f);
    int t = g;
    for (; t + 12 < L; t += 16) {
        int e0 = slist[t], e1 = slist[t + 4], e2 = slist[t + 8], e3 = slist[t + 12];
        const float* r0 = (e0 & SFLAG) ? &sbase[((e0 & 0xFFFF) - 32) * Dd] : &hbase[e0 * Dd];
        const float* r1 = (e1 & SFLAG) ? &sbase[((e1 & 0xFFFF) - 32) * Dd] : &hbase[e1 * Dd];
        const float* r2 = (e2 & SFLAG) ? &sbase[((e2 & 0xFFFF) - 32) * Dd] : &hbase[e2 * Dd];
        const float* r3 = (e3 & SFLAG) ? &sbase[((e3 & 0xFFFF) - 32) * Dd] : &hbase[e3 * Dd];
        float4 v0 = *(const float4*)&r0[l * 4];
        float4 v1 = *(const float4*)&r1[l * 4];
        float4 v2 = *(const float4*)&r2[l * 4];
        float4 v3 = *(const float4*)&r3[l * 4];
        acc.x += (v0.x + v1.x) + (v2.x + v3.x);
        acc.y += (v0.y + v1.y) + (v2.y + v3.y);
        acc.z += (v0.z + v1.z) + (v2.z + v3.z);
        acc.w += (v0.w + v1.w) + (v2.w + v3.w);
    }
    for (; t < L; t += 4) {
        int e0 = slist[t];
        const float* r0 = (e0 & SFLAG) ? &sbase[((e0 & 0xFFFF) - 32) * Dd] : &hbase[e0 * Dd];
        float4 v0 = *(const float4*)&r0[l * 4];
        acc.x += v0.x; acc.y += v0.y; acc.z += v0.z; acc.w += v0.w;
    }
    *(float4*)&sbuf[g * Dd + l * 4] = acc;
    __syncthreads();
    float v = sbuf[tid] + sbuf[Dd + tid] + sbuf[2 * Dd + tid] + sbuf[3 * Dd + tid];
    g_agg[(bN + local) * Dd + tid] = v * sInv;
}

// ---------------------------------------------------------------------------
// x += agg @ W1 + bias + h @ W2, f32x2 packed FMA with zero in-loop packing.
// BM=64, BN=128 (full), BK=32, 128 threads, 8x8 micro-tile.
// FUSE: epilogue computes next layer's h = gelu(LN(x_new)) into g_h.
// ---------------------------------------------------------------------------
template<bool FUSE>
__global__ void __launch_bounds__(128) gemm_kernel(
    const float* __restrict__ W1, const float* __restrict__ W2,
    const float* __restrict__ bias,
    const float* __restrict__ gamma, const float* __restrict__ beta,
    float* __restrict__ X)
{
    __shared__ __align__(16) unsigned long long As2[32][64];   // 16 KB, (a,a) pairs
    __shared__ __align__(16) float Bs[32][128];                // 16 KB
    const int bm = blockIdx.x * 64;
    const int tid = threadIdx.x;
    const int trow = tid >> 4;   // 0..7
    const int tcol = tid & 15;   // 0..15
    const int tm = trow * 8;
    const int tn = tcol * 8;

    unsigned long long acc[8][4];
#pragma unroll
    for (int i = 0; i < 8; i++)
#pragma unroll
        for (int j = 0; j < 4; j++) acc[i][j] = 0ull;

#pragma unroll
    for (int pass = 0; pass < 2; pass++) {
        const float* A = pass ? g_h : g_agg;
        const float* W = pass ? W2 : W1;
#pragma unroll
        for (int k0 = 0; k0 < Dd; k0 += 32) {
            {
                int m = tid >> 1, half = tid & 1;
                const float* ap = &A[(bm + m) * Dd + k0 + half * 16];
                int kb = half * 16;
#pragma unroll
                for (int j = 0; j < 4; j++) {
                    float4 v = *(const float4*)(ap + j * 4);
                    As2[kb + j*4 + 0][m] = pack2(v.x, v.x);
                    As2[kb + j*4 + 1][m] = pack2(v.y, v.y);
                    As2[kb + j*4 + 2][m] = pack2(v.z, v.z);
                    As2[kb + j*4 + 3][m] = pack2(v.w, v.w);
                }
            }
            {
                int kk = tid >> 2, q = tid & 3;
                const float* wp = &W[(k0 + kk) * Dd + q * 32];
#pragma unroll
                for (int j = 0; j < 8; j++)
                    *(float4*)&Bs[kk][q * 32 + j * 4] = *(const float4*)(wp + j * 4);
            }
            __syncthreads();
#pragma unroll
            for (int kk = 0; kk < 32; kk++) {
                ulonglong2 a01 = *(const ulonglong2*)&As2[kk][tm];
                ulonglong2 a23 = *(const ulonglong2*)&As2[kk][tm + 2];
                ulonglong2 a45 = *(const ulonglong2*)&As2[kk][tm + 4];
                ulonglong2 a67 = *(const ulonglong2*)&As2[kk][tm + 6];
                ulonglong2 b01 = *(const ulonglong2*)&Bs[kk][tn];
                ulonglong2 b23 = *(const ulonglong2*)&Bs[kk][tn + 4];
                unsigned long long ap[8] = {a01.x, a01.y, a23.x, a23.y,
                                            a45.x, a45.y, a67.x, a67.y};
                unsigned long long bp[4] = {b01.x, b01.y, b23.x, b23.y};
#pragma unroll
                for (int i = 0; i < 8; i++) {
                    ffma2(acc[i][0], ap[i], bp[0]);
                    ffma2(acc[i][1], ap[i], bp[1]);
                    ffma2(acc[i][2], ap[i], bp[2]);
                    ffma2(acc[i][3], ap[i], bp[3]);
                }
            }
            __syncthreads();
        }
    }

    // Epilogue
    float bb[8], gg[8], be[8];
#pragma unroll
    for (int j = 0; j < 8; j++) bb[j] = bias[tn + j];
    if (FUSE) {
#pragma unroll
        for (int j = 0; j < 8; j++) { gg[j] = gamma[tn + j]; be[j] = beta[tn + j]; }
    }
#pragma unroll
    for (int i = 0; i < 8; i++) {
        int row = bm + tm + i;
        float4 x0 = *(const float4*)&X[row * Dd + tn];
        float4 x1 = *(const float4*)&X[row * Dd + tn + 4];
        float xv[8] = {x0.x, x0.y, x0.z, x0.w, x1.x, x1.y, x1.z, x1.w};
#pragma unroll
        for (int j = 0; j < 4; j++) {
            float lo, hi;
            unpack2(acc[i][j], lo, hi);
            xv[2*j]   += lo + bb[2*j];
            xv[2*j+1] += hi + bb[2*j+1];
        }
        x0 = make_float4(xv[0], xv[1], xv[2], xv[3]);
        x1 = make_float4(xv[4], xv[5], xv[6], xv[7]);
        *(float4*)&X[row * Dd + tn]     = x0;
        *(float4*)&X[row * Dd + tn + 4] = x1;
        if (FUSE) {
            float s = 0.f, s2 = 0.f;
#pragma unroll
            for (int j = 0; j < 8; j++) { s += xv[j]; s2 += xv[j] * xv[j]; }
#pragma unroll
            for (int o = 1; o <= 8; o <<= 1) {
                s  += __shfl_xor_sync(0xffffffffu, s, o);
                s2 += __shfl_xor_sync(0xffffffffu, s2, o);
            }
            float mu  = s * (1.0f / 128.0f);
            float var = s2 * (1.0f / 128.0f) - mu * mu;
            float rs  = rsqrtf(var + 1e-5f);
            float hv[8];
#pragma unroll
            for (int j = 0; j < 8; j++) {
                float t = (xv[j] - mu) * rs * gg[j] + be[j];
                hv[j] = 0.5f * t * (1.0f + erff(t * 0.70710678118654752f));
            }
            *(float4*)&g_h[row * Dd + tn]     = make_float4(hv[0], hv[1], hv[2], hv[3]);
            *(float4*)&g_h[row * Dd + tn + 4] = make_float4(hv[4], hv[5], hv[6], hv[7]);
        }
    }
}

// ---------------------------------------------------------------------------
extern "C" void kernel_launch(void* const* d_in, const int* in_sizes, int n_in,
                              void* d_out, int out_size) {
    const float* elements = (const float*)d_in[0];
    const float* ln_gamma = (const float*)d_in[1];
    const float* ln_beta  = (const float*)d_in[2];
    const float* w_nei    = (const float*)d_in[3];
    const float* b_nei    = (const float*)d_in[4];
    const float* w_root   = (const float*)d_in[5];
    float* x = (float*)d_out;

    tree1_kernel<<<Bb * 32, Dd>>>(elements);                       // 1
    tree2_kernel<<<Bb, Dd>>>();                                    // 2
    encx_kernel<<<BN, Dd>>>(x, ln_gamma, ln_beta);                 // 3

    // layer 0 (gemm fuses LN+GELU for layer 1 into its epilogue)
    s1_kernel<<<264, Dd>>>();                                      // 4 (profiled)
    aggall_kernel<<<8192 + Bb * 31, Dd>>>();                       // 5
    gemm_kernel<true><<<BN / 64, 128>>>(w_nei, w_root, b_nei,
                                        ln_gamma + Dd, ln_beta + Dd, x);

    // layer 1 (final — no fused LN)
    s1_kernel<<<264, Dd>>>();
    aggall_kernel<<<8192 + Bb * 31, Dd>>>();
    gemm_kernel<false><<<BN / 64, 128>>>(w_nei + Dd * Dd, w_root + Dd * Dd,
                                         b_nei + Dd, nullptr, nullptr, x);
}